// round 5
// baseline (speedup 1.0000x reference)
#include <cuda_runtime.h>

// Problem constants (B,H,S,D) = (4,16,2048,64), fp32 in/out.
#define NB 4
#define NH 16
#define NS 2048
#define ND 64
#define BM 128      // query rows per CTA (one row per thread)
#define TN 64       // key tile staged in SMEM
#define CH 8        // softmax rescale chunk
#define SCALE 0.125f  // 1/sqrt(64)

// Scratch for mean-of-V (invalid rows output). Allocation-free per harness rules.
__device__ float g_vmean[NB * NH * ND];

// vmean[bh][d] = (1/S) * sum_k V[bh][k][d]
__global__ void vmean_kernel(const float* __restrict__ V) {
    const int bh = blockIdx.x;   // 64 blocks
    const int d  = threadIdx.x;  // 64 threads
    const float* vp = V + (size_t)bh * NS * ND + d;
    float s = 0.f;
#pragma unroll 8
    for (int i = 0; i < NS; ++i) s += vp[(size_t)i * ND];
    g_vmean[bh * ND + d] = s * (1.0f / NS);
}

__global__ void __launch_bounds__(BM, 2)
attn_kernel(const float* __restrict__ Q, const float* __restrict__ K,
            const float* __restrict__ V, const int* __restrict__ EL,
            float* __restrict__ O) {
    __shared__ float ks[TN][ND];
    __shared__ float vs[TN][ND];

    const int bh  = blockIdx.y;
    const int b   = bh / NH;
    const int el  = EL[b];                         // uniform per CTA
    const int row = blockIdx.x * BM + threadIdx.x; // this thread's query row
    const size_t base = (size_t)bh * NS * ND;
    float4* op = (float4*)(O + base + (size_t)row * ND);

    // Whole query tile invalid -> every row outputs mean(V). Uniform branch.
    if (blockIdx.x * BM >= el) {
        const float4* vm = (const float4*)(g_vmean + bh * ND);
#pragma unroll
        for (int i = 0; i < ND / 4; ++i) op[i] = vm[i];
        return;
    }

    // Q row in registers (16 float4 = 64 regs)
    float4 qr[ND / 4];
    {
        const float4* qp = (const float4*)(Q + base + (size_t)row * ND);
#pragma unroll
        for (int i = 0; i < ND / 4; ++i) qr[i] = qp[i];
    }

    // Output accumulator (64 regs) + online-softmax state
    float4 o4[ND / 4];
#pragma unroll
    for (int i = 0; i < ND / 4; ++i) o4[i] = make_float4(0.f, 0.f, 0.f, 0.f);
    float m = -1e30f, l = 0.f;

    const int elfull = el & ~(TN - 1);
    const float4* ks4 = (const float4*)&ks[0][0];
    const float4* vs4 = (const float4*)&vs[0][0];

    // ---- full key tiles [0, elfull) ----
    for (int j0 = 0; j0 < elfull; j0 += TN) {
        __syncthreads();
        {
            const float4* kp = (const float4*)(K + base + (size_t)j0 * ND);
            const float4* vp = (const float4*)(V + base + (size_t)j0 * ND);
            float4* ksd = (float4*)&ks[0][0];
            float4* vsd = (float4*)&vs[0][0];
#pragma unroll
            for (int i = 0; i < (TN * ND / 4) / BM; ++i) {
                int idx = i * BM + threadIdx.x; // coalesced float4
                ksd[idx] = kp[idx];
                vsd[idx] = vp[idx];
            }
        }
        __syncthreads();

#pragma unroll 1
        for (int c = 0; c < TN; c += CH) {
            // 1) dots for CH keys (K reads are warp-uniform -> SMEM broadcast)
            float sreg[CH];
#pragma unroll
            for (int t = 0; t < CH; ++t) {
                float a0 = 0.f, a1 = 0.f, a2 = 0.f, a3 = 0.f;
#pragma unroll
                for (int i = 0; i < ND / 4; ++i) {
                    float4 kv = ks4[(c + t) * (ND / 4) + i];
                    a0 = fmaf(qr[i].x, kv.x, a0);
                    a1 = fmaf(qr[i].y, kv.y, a1);
                    a2 = fmaf(qr[i].z, kv.z, a2);
                    a3 = fmaf(qr[i].w, kv.w, a3);
                }
                sreg[t] = ((a0 + a1) + (a2 + a3)) * SCALE;
            }
            // 2) one rescale per chunk
            float mc = sreg[0];
#pragma unroll
            for (int t = 1; t < CH; ++t) mc = fmaxf(mc, sreg[t]);
            float mn = fmaxf(m, mc);
            float corr = __expf(m - mn);
            l *= corr;
#pragma unroll
            for (int i = 0; i < ND / 4; ++i) {
                o4[i].x *= corr; o4[i].y *= corr;
                o4[i].z *= corr; o4[i].w *= corr;
            }
            // 3) accumulate P*V
#pragma unroll
            for (int t = 0; t < CH; ++t) {
                float p = __expf(sreg[t] - mn);
                l += p;
#pragma unroll
                for (int i = 0; i < ND / 4; ++i) {
                    float4 vv = vs4[(c + t) * (ND / 4) + i];
                    o4[i].x = fmaf(p, vv.x, o4[i].x);
                    o4[i].y = fmaf(p, vv.y, o4[i].y);
                    o4[i].z = fmaf(p, vv.z, o4[i].z);
                    o4[i].w = fmaf(p, vv.w, o4[i].w);
                }
            }
            m = mn;
        }
    }

    // ---- tail keys [elfull, el), < TN of them; runs at most once ----
    if (elfull < el) {
        __syncthreads();
        {
            const float4* kp = (const float4*)(K + base + (size_t)elfull * ND);
            const float4* vp = (const float4*)(V + base + (size_t)elfull * ND);
            float4* ksd = (float4*)&ks[0][0];
            float4* vsd = (float4*)&vs[0][0];
#pragma unroll
            for (int i = 0; i < (TN * ND / 4) / BM; ++i) {
                int idx = i * BM + threadIdx.x; // elfull+TN <= NS always
                ksd[idx] = kp[idx];
                vsd[idx] = vp[idx];
            }
        }
        __syncthreads();
        const int r = el - elfull;
#pragma unroll 1
        for (int t = 0; t < r; ++t) {
            float a0 = 0.f, a1 = 0.f, a2 = 0.f, a3 = 0.f;
#pragma unroll
            for (int i = 0; i < ND / 4; ++i) {
                float4 kv = ks4[t * (ND / 4) + i];
                a0 = fmaf(qr[i].x, kv.x, a0);
                a1 = fmaf(qr[i].y, kv.y, a1);
                a2 = fmaf(qr[i].z, kv.z, a2);
                a3 = fmaf(qr[i].w, kv.w, a3);
            }
            float sv = ((a0 + a1) + (a2 + a3)) * SCALE;
            float mn = fmaxf(m, sv);
            float corr = __expf(m - mn);
            float p = __expf(sv - mn);
            l = l * corr + p;
#pragma unroll
            for (int i = 0; i < ND / 4; ++i) {
                float4 vv = vs4[t * (ND / 4) + i];
                o4[i].x = fmaf(p, vv.x, o4[i].x * corr);
                o4[i].y = fmaf(p, vv.y, o4[i].y * corr);
                o4[i].z = fmaf(p, vv.z, o4[i].z * corr);
                o4[i].w = fmaf(p, vv.w, o4[i].w * corr);
            }
            m = mn;
        }
    }

    // ---- epilogue ----
    if (row < el) {
        float rl = 1.0f / l;
#pragma unroll
        for (int i = 0; i < ND / 4; ++i) {
            float4 r4 = o4[i];
            r4.x *= rl; r4.y *= rl; r4.z *= rl; r4.w *= rl;
            op[i] = r4;
        }
    } else {
        // invalid row inside a partially-valid tile: exact reference semantics
        const float4* vm = (const float4*)(g_vmean + bh * ND);
#pragma unroll
        for (int i = 0; i < ND / 4; ++i) op[i] = vm[i];
    }
}

extern "C" void kernel_launch(void* const* d_in, const int* in_sizes, int n_in,
                              void* d_out, int out_size) {
    const float* q  = (const float*)d_in[0];
    const float* k  = (const float*)d_in[1];
    const float* v  = (const float*)d_in[2];
    const int*   el = (const int*)d_in[3];
    float* out = (float*)d_out;

    vmean_kernel<<<NB * NH, ND>>>(v);           // writes g_vmean
    dim3 grid(NS / BM, NB * NH);
    attn_kernel<<<grid, BM>>>(q, k, v, el, out); // stream-ordered after vmean
}

// round 6
// speedup vs baseline: 1.2344x; 1.2344x over previous
#include <cuda_runtime.h>

// (B,H,S,D) = (4,16,2048,64), fp32 in/out.
#define NB 4
#define NH 16
#define NS 2048
#define ND 64
#define BM 128      // query rows per CTA (one per thread)
#define TN 64       // key tile staged in SMEM
#define CH 8        // softmax rescale chunk
// Pre-fold 1/sqrt(D) and log2(e) into Q so scores are in log2 domain.
#define QS (0.125f * 1.4426950408889634f)

typedef unsigned long long u64;

__device__ float g_vmean[NB * NH * ND];

// vmean[bh][d] = (1/S) * sum_k V[bh][k][d]  (output for invalid query rows)
__global__ void vmean_kernel(const float* __restrict__ V) {
    const int bh = blockIdx.x;
    const int d  = threadIdx.x;
    const float* vp = V + (size_t)bh * NS * ND + d;
    float s = 0.f;
#pragma unroll 8
    for (int i = 0; i < NS; ++i) s += vp[(size_t)i * ND];
    g_vmean[bh * ND + d] = s * (1.0f / NS);
}

// ---- packed fp32x2 helpers (sm_100+ only; 2 fp32 lanes per FMA issue) ----
__device__ __forceinline__ void fma2(u64& d, u64 a, u64 b) {
    asm("fma.rn.f32x2 %0, %1, %2, %0;" : "+l"(d) : "l"(a), "l"(b));
}
__device__ __forceinline__ u64 add2(u64 a, u64 b) {
    u64 d; asm("add.rn.f32x2 %0, %1, %2;" : "=l"(d) : "l"(a), "l"(b)); return d;
}
__device__ __forceinline__ u64 mul2(u64 a, u64 b) {
    u64 d; asm("mul.rn.f32x2 %0, %1, %2;" : "=l"(d) : "l"(a), "l"(b)); return d;
}
__device__ __forceinline__ u64 pack2(float x, float y) {
    u64 d; asm("mov.b64 %0, {%1, %2};" : "=l"(d) : "f"(x), "f"(y)); return d;
}
__device__ __forceinline__ float2 unpack2(u64 a) {
    float2 r; asm("mov.b64 {%0, %1}, %2;" : "=f"(r.x), "=f"(r.y) : "l"(a)); return r;
}

__global__ void __launch_bounds__(BM, 3)
attn_kernel(const float* __restrict__ Q, const float* __restrict__ K,
            const float* __restrict__ V, const int* __restrict__ EL,
            float* __restrict__ O) {
    __shared__ u64 ks[TN * ND / 2];   // 16 KB, packed float pairs
    __shared__ u64 vs[TN * ND / 2];   // 16 KB

    const int bh  = blockIdx.y;
    const int b   = bh / NH;
    const int el  = EL[b];                         // uniform per CTA
    const int row = blockIdx.x * BM + threadIdx.x;
    const size_t base = (size_t)bh * NS * ND;
    ulonglong2* op = (ulonglong2*)(O + base + (size_t)row * ND);

    // Fully-invalid query tile: every row outputs mean(V). Uniform branch.
    if (blockIdx.x * BM >= el) {
        const ulonglong2* vm = (const ulonglong2*)(g_vmean + bh * ND);
#pragma unroll
        for (int i = 0; i < ND / 4; ++i) op[i] = vm[i];
        return;
    }

    // Q row, pre-scaled by (1/sqrt(D))*log2(e), packed: 32 u64 = 64 regs
    u64 qr[ND / 2];
    {
        const float4* qp = (const float4*)(Q + base + (size_t)row * ND);
#pragma unroll
        for (int i = 0; i < ND / 4; ++i) {
            float4 t = qp[i];
            qr[2 * i]     = pack2(t.x * QS, t.y * QS);
            qr[2 * i + 1] = pack2(t.z * QS, t.w * QS);
        }
    }

    // Packed output accumulator (64 regs) + online-softmax state (log2 domain)
    u64 o2[ND / 2];
#pragma unroll
    for (int i = 0; i < ND / 2; ++i) o2[i] = 0ull;   // bit pattern of (0.f,0.f)
    float m = -1e30f, l = 0.f;

    const int elfull = el & ~(TN - 1);

    // ---- full key tiles [0, elfull) ----
    for (int j0 = 0; j0 < elfull; j0 += TN) {
        __syncthreads();
        {
            const ulonglong2* kp = (const ulonglong2*)(K + base + (size_t)j0 * ND);
            const ulonglong2* vp = (const ulonglong2*)(V + base + (size_t)j0 * ND);
            ulonglong2* ksd = (ulonglong2*)ks;
            ulonglong2* vsd = (ulonglong2*)vs;
#pragma unroll
            for (int i = 0; i < (TN * ND / 4) / BM; ++i) {
                int idx = i * BM + threadIdx.x;   // coalesced 16B
                ksd[idx] = kp[idx];
                vsd[idx] = vp[idx];
            }
        }
        __syncthreads();

#pragma unroll 1
        for (int c = 0; c < TN; c += CH) {
            // 1) dots for CH keys: 32 packed FMA each (broadcast LDS.128)
            float sreg[CH];
#pragma unroll
            for (int t = 0; t < CH; ++t) {
                const ulonglong2* kk = (const ulonglong2*)(ks + (c + t) * (ND / 2));
                u64 a0 = 0ull, a1 = 0ull, a2 = 0ull, a3 = 0ull;
#pragma unroll
                for (int i = 0; i < ND / 4; i += 2) {
                    ulonglong2 k0 = kk[i], k1 = kk[i + 1];
                    fma2(a0, qr[2 * i],     k0.x);
                    fma2(a1, qr[2 * i + 1], k0.y);
                    fma2(a2, qr[2 * i + 2], k1.x);
                    fma2(a3, qr[2 * i + 3], k1.y);
                }
                float2 f = unpack2(add2(add2(a0, a1), add2(a2, a3)));
                sreg[t] = f.x + f.y;     // score in log2 domain
            }
            // 2) one rescale per chunk
            float mc = sreg[0];
#pragma unroll
            for (int t = 1; t < CH; ++t) mc = fmaxf(mc, sreg[t]);
            float mn = fmaxf(m, mc);
            float corr = exp2f(m - mn);
            l *= corr;
            u64 c2 = pack2(corr, corr);
#pragma unroll
            for (int i = 0; i < ND / 2; ++i) o2[i] = mul2(o2[i], c2);
            // 3) accumulate P*V
#pragma unroll
            for (int t = 0; t < CH; ++t) {
                float p = exp2f(sreg[t] - mn);
                l += p;
                u64 p2 = pack2(p, p);
                const ulonglong2* vv = (const ulonglong2*)(vs + (c + t) * (ND / 2));
#pragma unroll
                for (int i = 0; i < ND / 4; i += 2) {
                    ulonglong2 v0 = vv[i], v1 = vv[i + 1];
                    fma2(o2[2 * i],     p2, v0.x);
                    fma2(o2[2 * i + 1], p2, v0.y);
                    fma2(o2[2 * i + 2], p2, v1.x);
                    fma2(o2[2 * i + 3], p2, v1.y);
                }
            }
            m = mn;
        }
    }

    // ---- tail keys [elfull, el); runs at most once, < TN keys ----
    if (elfull < el) {
        __syncthreads();
        {
            const ulonglong2* kp = (const ulonglong2*)(K + base + (size_t)elfull * ND);
            const ulonglong2* vp = (const ulonglong2*)(V + base + (size_t)elfull * ND);
            ulonglong2* ksd = (ulonglong2*)ks;
            ulonglong2* vsd = (ulonglong2*)vs;
#pragma unroll
            for (int i = 0; i < (TN * ND / 4) / BM; ++i) {
                int idx = i * BM + threadIdx.x;   // elfull+TN <= NS always
                ksd[idx] = kp[idx];
                vsd[idx] = vp[idx];
            }
        }
        __syncthreads();
        const int r = el - elfull;
#pragma unroll 1
        for (int t = 0; t < r; ++t) {
            const ulonglong2* kk = (const ulonglong2*)(ks + t * (ND / 2));
            u64 a0 = 0ull, a1 = 0ull, a2 = 0ull, a3 = 0ull;
#pragma unroll
            for (int i = 0; i < ND / 4; i += 2) {
                ulonglong2 k0 = kk[i], k1 = kk[i + 1];
                fma2(a0, qr[2 * i],     k0.x);
                fma2(a1, qr[2 * i + 1], k0.y);
                fma2(a2, qr[2 * i + 2], k1.x);
                fma2(a3, qr[2 * i + 3], k1.y);
            }
            float2 f = unpack2(add2(add2(a0, a1), add2(a2, a3)));
            float sv = f.x + f.y;
            float mn = fmaxf(m, sv);
            float corr = exp2f(m - mn);
            float p = exp2f(sv - mn);
            l = l * corr + p;
            u64 c2 = pack2(corr, corr);
            u64 p2 = pack2(p, p);
            const ulonglong2* vv = (const ulonglong2*)(vs + t * (ND / 2));
#pragma unroll
            for (int i = 0; i < ND / 4; i += 2) {
                ulonglong2 v0 = vv[i], v1 = vv[i + 1];
                o2[2 * i]     = mul2(o2[2 * i],     c2);
                o2[2 * i + 1] = mul2(o2[2 * i + 1], c2);
                o2[2 * i + 2] = mul2(o2[2 * i + 2], c2);
                o2[2 * i + 3] = mul2(o2[2 * i + 3], c2);
                fma2(o2[2 * i],     p2, v0.x);
                fma2(o2[2 * i + 1], p2, v0.y);
                fma2(o2[2 * i + 2], p2, v1.x);
                fma2(o2[2 * i + 3], p2, v1.y);
            }
            m = mn;
        }
    }

    // ---- epilogue ----
    if (row < el) {
        float rl = 1.0f / l;
        u64 rl2 = pack2(rl, rl);
#pragma unroll
        for (int i = 0; i < ND / 4; ++i) {
            ulonglong2 w;
            w.x = mul2(o2[2 * i],     rl2);
            w.y = mul2(o2[2 * i + 1], rl2);
            op[i] = w;
        }
    } else {
        // invalid row inside a partially-valid tile: exact reference semantics
        const ulonglong2* vm = (const ulonglong2*)(g_vmean + bh * ND);
#pragma unroll
        for (int i = 0; i < ND / 4; ++i) op[i] = vm[i];
    }
}

extern "C" void kernel_launch(void* const* d_in, const int* in_sizes, int n_in,
                              void* d_out, int out_size) {
    const float* q  = (const float*)d_in[0];
    const float* k  = (const float*)d_in[1];
    const float* v  = (const float*)d_in[2];
    const int*   el = (const int*)d_in[3];
    float* out = (float*)d_out;

    vmean_kernel<<<NB * NH, ND>>>(v);            // writes g_vmean
    dim3 grid(NS / BM, NB * NH);
    attn_kernel<<<grid, BM>>>(q, k, v, el, out); // stream-ordered after vmean
}